// round 14
// baseline (speedup 1.0000x reference)
#include <cuda_runtime.h>
#include <cuda_fp16.h>
#include <math.h>

// ConvCaps EM routing (b=8, B=C=32, K=3, s=2, Win=13, Wout=6, 3 EM iters).
// R14: split at the former grid-barrier points into 3 kernels so the 4
// vote-READ sweeps run at 24 warps/SM (384 thr, 85-reg cap) instead of being
// pinned to 16 warps/SM by M0's 128-reg compute sweep.
//   kA: M0 (compute votes fp32, cache fp16) + stats + E0 (stream cache,
//       p_hat -> global, D0 via warp-shuffle + atomicAdd).
//   kB: M1 (stream votes+p_hat) + stats + E1 (-> D1, p_hat).
//   kC: M2 + output.
// Kernel boundaries provide the cross-block D ordering (no grid barrier).

#define RP0 (1.0f / 1152.0f)
#define LOG2PI 1.8378770664093453f
typedef unsigned long long ull;

__device__ float g_Wt[147456];        // [o][ij][q][c][p]  (ulonglong2 per (q,c))
__device__ __half g_votes[42467328];  // [n][xy][oij][g][c][8]  85 MB, L2-resident
__device__ float g_ph[2654208];       // [n][xy][oij][c]  10.6 MB
__device__ float g_D0[43264];         // [n][o][13][13]
__device__ float g_D1[43264];

// -------- prep: W relayout, zero D --------
__global__ void prep_kernel(const float* __restrict__ W) {
    int idx = blockIdx.x * 256 + threadIdx.x;
    if (idx < 147456) {
        int p = idx & 3, c = (idx >> 2) & 31, q = (idx >> 7) & 3;
        int oij = idx >> 9;
        int o = oij / 9, ij = oij - o * 9;
        // src: W[i,j,o,c,p,q]
        g_Wt[idx] = W[(((ij * 32 + o) * 32 + c) * 4 + p) * 4 + q];
    }
    if (idx < 43264) { g_D0[idx] = 0.0f; g_D1[idx] = 0.0f; }
}

// -------- packed f32x2 helpers --------
__device__ __forceinline__ ull f2fma(ull a, ull b, ull c) {
    ull d; asm("fma.rn.f32x2 %0, %1, %2, %3;" : "=l"(d) : "l"(a), "l"(b), "l"(c)); return d;
}
__device__ __forceinline__ ull f2mul(ull a, ull b) {
    ull d; asm("mul.rn.f32x2 %0, %1, %2;" : "=l"(d) : "l"(a), "l"(b)); return d;
}
__device__ __forceinline__ ull f2add(ull a, ull b) {
    ull d; asm("add.rn.f32x2 %0, %1, %2;" : "=l"(d) : "l"(a), "l"(b)); return d;
}
__device__ __forceinline__ ull f2pack(float lo, float hi) {
    ull d; asm("mov.b64 %0, {%1, %2};" : "=l"(d) : "f"(lo), "f"(hi)); return d;
}
__device__ __forceinline__ void f2unpack(float& lo, float& hi, ull v) {
    asm("mov.b64 {%0, %1}, %2;" : "=f"(lo), "=f"(hi) : "l"(v));
}
__device__ __forceinline__ unsigned f2h2(ull v) {    // packed f32x2 -> half2
    float lo, hi; f2unpack(lo, hi, v);
    unsigned r; asm("cvt.rn.f16x2.f32 %0, %1, %2;" : "=r"(r) : "f"(hi), "f"(lo));
    return r;
}
__device__ __forceinline__ ull h2w(unsigned u) {     // half2 -> packed f32x2
    __half2 h = *reinterpret_cast<__half2*>(&u);
    float2 f = __half22float2(h);
    return f2pack(f.x, f.y);
}

// ---- shared stats helper (tid<32 path) ----
__device__ __forceinline__ void stats_c(
    const float* mm, float bv, float ba, float lam,
    float* mu_c /*17*/, float& sfac, float* out_on /*nullptr if not last*/)
{
    float R = mm[32];
    float invR = 1.0f / R;
    float cs = 0.0f;
    #pragma unroll
    for (int d = 0; d < 16; d++) {
        float m  = mm[d] * invR;
        float sg = fmaf(-m, m, mm[16 + d] * invR);
        mu_c[d] = m;
        cs += __logf(sg);
    }
    float cost = R * fmaf(16.0f, bv, cs);
    float act  = 1.0f / (1.0f + __expf(lam * (cost - ba)));
    if (out_on) {
        #pragma unroll
        for (int d = 0; d < 16; d++) out_on[d * 16 * 36] = mu_c[d];  // placeholder (unused)
    }
    sfac = act * __expf(-0.5f * fmaf(16.0f, LOG2PI, cs));
    (void)act;
}

// ===================== kernel A: M0 + E0 =====================
// smem: pose2 9216 | aD 288 | red 8448 | mom 1056 | mu 544 | sfac 32 = 19584 f
#define SMA_POSE2 0
#define SMA_AD    9216
#define SMA_RED   9504
#define SMA_MOM   17952
#define SMA_MU    19008
#define SMA_SFAC  19552
#define SMA_FLOATS 19584

__global__ void __launch_bounds__(256, 2) kA(
    const float* __restrict__ x,
    const float* __restrict__ bv_p,
    const float* __restrict__ ba_p,
    const float* __restrict__ lam_p)
{
    extern __shared__ float sm[];
    float* pose2  = sm + SMA_POSE2;
    float* aD_s   = sm + SMA_AD;
    float* red    = sm + SMA_RED;
    float* mom    = sm + SMA_MOM;
    float* mu_s   = sm + SMA_MU;
    float* sfac_s = sm + SMA_SFAC;

    const int xy = blockIdx.x, n = blockIdx.y;
    const int X = xy / 6, Y = xy % 6;
    const int tid = threadIdx.x;
    const int w = tid >> 5, c = tid & 31;
    const float* xn = x + n * (544 * 169);
    const int base = (2 * X) * 13 + 2 * Y;

    for (int e = tid; e < 512; e += 256) {
        int qr = e & 15, o = e >> 4;
        const float* src = xn + (qr * 32 + o) * 169 + base;
        #pragma unroll
        for (int i = 0; i < 3; i++)
            #pragma unroll
            for (int j = 0; j < 3; j++) {
                float v = src[i * 13 + j];
                int off = (o * 9 + i * 3 + j) * 32 + qr * 2;
                pose2[off] = v; pose2[off + 1] = v;
            }
    }
    for (int e = tid; e < 288; e += 256) {
        int o = e / 9, ij = e - o * 9;
        aD_s[e] = xn[(512 + o) * 169 + base + (ij / 3) * 13 + (ij % 3)] * RP0;
    }
    __syncthreads();

    const float bv = bv_p[0], ba = ba_p[0], lam = lam_p[0];
    const ulonglong2* wbase = (const ulonglong2*)g_Wt + (w * 36 * 4) * 32 + c;
    uint4* vb = (uint4*)g_votes + (((n * 36 + xy) * 288 + w * 36) * 2) * 32 + c;

    // ---- M0: compute votes (W prefetch d=1), cache fp16, moments ----
    ull m1a[4], m1b[4], m2a[4], m2b[4];
    #pragma unroll
    for (int r = 0; r < 4; r++) { m1a[r]=0ull; m1b[r]=0ull; m2a[r]=0ull; m2b[r]=0ull; }
    float sumr = 0.0f;
    {
        ulonglong2 wv0 = wbase[0], wv1 = wbase[32], wv2 = wbase[64], wv3 = wbase[96];
        #pragma unroll 2
        for (int k = 0; k < 36; k++) {
            ulonglong2 n0 = wv0, n1 = wv1, n2 = wv2, n3 = wv3;
            if (k < 35) {
                const ulonglong2* nw = wbase + (k + 1) * 128;
                n0 = nw[0]; n1 = nw[32]; n2 = nw[64]; n3 = nw[96];
            }
            int oij = w * 36 + k;
            float rh = aD_s[oij];
            sumr += rh;
            ull rh2 = f2pack(rh, rh);
            const ulonglong2* pb2 = (const ulonglong2*)(pose2 + oij * 32);
            ull v0[4], v1[4];
            {
                ulonglong2 pA = pb2[0], pB = pb2[1];
                v0[0] = f2mul(wv0.x, pA.x); v1[0] = f2mul(wv0.y, pA.x);
                v0[1] = f2mul(wv0.x, pA.y); v1[1] = f2mul(wv0.y, pA.y);
                v0[2] = f2mul(wv0.x, pB.x); v1[2] = f2mul(wv0.y, pB.x);
                v0[3] = f2mul(wv0.x, pB.y); v1[3] = f2mul(wv0.y, pB.y);
            }
            {
                ulonglong2 pA = pb2[2], pB = pb2[3];
                v0[0] = f2fma(wv1.x, pA.x, v0[0]); v1[0] = f2fma(wv1.y, pA.x, v1[0]);
                v0[1] = f2fma(wv1.x, pA.y, v0[1]); v1[1] = f2fma(wv1.y, pA.y, v1[1]);
                v0[2] = f2fma(wv1.x, pB.x, v0[2]); v1[2] = f2fma(wv1.y, pB.x, v1[2]);
                v0[3] = f2fma(wv1.x, pB.y, v0[3]); v1[3] = f2fma(wv1.y, pB.y, v1[3]);
            }
            {
                ulonglong2 pA = pb2[4], pB = pb2[5];
                v0[0] = f2fma(wv2.x, pA.x, v0[0]); v1[0] = f2fma(wv2.y, pA.x, v1[0]);
                v0[1] = f2fma(wv2.x, pA.y, v0[1]); v1[1] = f2fma(wv2.y, pA.y, v1[1]);
                v0[2] = f2fma(wv2.x, pB.x, v0[2]); v1[2] = f2fma(wv2.y, pB.x, v1[2]);
                v0[3] = f2fma(wv2.x, pB.y, v0[3]); v1[3] = f2fma(wv2.y, pB.y, v1[3]);
            }
            {
                ulonglong2 pA = pb2[6], pB = pb2[7];
                v0[0] = f2fma(wv3.x, pA.x, v0[0]); v1[0] = f2fma(wv3.y, pA.x, v1[0]);
                v0[1] = f2fma(wv3.x, pA.y, v0[1]); v1[1] = f2fma(wv3.y, pA.y, v1[1]);
                v0[2] = f2fma(wv3.x, pB.x, v0[2]); v1[2] = f2fma(wv3.y, pB.x, v1[2]);
                v0[3] = f2fma(wv3.x, pB.y, v0[3]); v1[3] = f2fma(wv3.y, pB.y, v1[3]);
            }
            uint4 s0, s1;
            s0.x = f2h2(v0[0]); s0.y = f2h2(v0[1]); s0.z = f2h2(v0[2]); s0.w = f2h2(v0[3]);
            s1.x = f2h2(v1[0]); s1.y = f2h2(v1[1]); s1.z = f2h2(v1[2]); s1.w = f2h2(v1[3]);
            vb[k * 64] = s0; vb[k * 64 + 32] = s1;
            #pragma unroll
            for (int r = 0; r < 4; r++) {
                ull t0 = f2mul(rh2, v0[r]);
                m1a[r] = f2add(m1a[r], t0);
                m2a[r] = f2fma(t0, v0[r], m2a[r]);
                ull t1 = f2mul(rh2, v1[r]);
                m1b[r] = f2add(m1b[r], t1);
                m2b[r] = f2fma(t1, v1[r], m2b[r]);
            }
            wv0 = n0; wv1 = n1; wv2 = n2; wv3 = n3;
        }
    }
    // reduce (8 warps)
    {
        float* myred = red + (w * 32 + c) * 33;
        #pragma unroll
        for (int r = 0; r < 4; r++) {
            float lo, hi;
            f2unpack(lo, hi, m1a[r]); myred[r]      = lo; myred[4 + r]  = hi;
            f2unpack(lo, hi, m1b[r]); myred[8 + r]  = lo; myred[12 + r] = hi;
            f2unpack(lo, hi, m2a[r]); myred[16 + r] = lo; myred[20 + r] = hi;
            f2unpack(lo, hi, m2b[r]); myred[24 + r] = lo; myred[28 + r] = hi;
        }
        myred[32] = sumr;
    }
    __syncthreads();
    for (int s = tid; s < 1056; s += 256) {
        float acc = 0.0f;
        #pragma unroll
        for (int ww = 0; ww < 8; ww++) acc += red[ww * 1056 + s];
        mom[s] = acc;
    }
    __syncthreads();
    if (tid < 32) {
        const float* mm = mom + tid * 33;
        float R = mm[32], invR = 1.0f / R, cs = 0.0f;
        #pragma unroll
        for (int d = 0; d < 16; d++) {
            float m  = mm[d] * invR;
            float sg = fmaf(-m, m, mm[16 + d] * invR);
            mu_s[tid * 17 + d] = m;
            cs += __logf(sg);
        }
        float cost = R * fmaf(16.0f, bv, cs);
        float act  = 1.0f / (1.0f + __expf(lam * (cost - ba)));
        sfac_s[tid] = act * __expf(-0.5f * fmaf(16.0f, LOG2PI, cs));
    }
    __syncthreads();

    // ---- E0: stream cached votes, p_hat -> global, D0 via shuffle ----
    {
        float sf = sfac_s[c];
        ull nmu0[4], nmu1[4];
        #pragma unroll
        for (int r = 0; r < 4; r++) {
            nmu0[r] = f2pack(-mu_s[c * 17 + r],     -mu_s[c * 17 + 4 + r]);
            nmu1[r] = f2pack(-mu_s[c * 17 + 8 + r], -mu_s[c * 17 + 12 + r]);
        }
        float* phb = g_ph + ((n * 36 + xy) * 288) * 32 + c;
        uint4 a0 = __ldcg(vb), a1 = __ldcg(vb + 32);
        #pragma unroll 4
        for (int k = 0; k < 36; k++) {
            uint4 b0 = a0, b1 = a1;
            if (k < 35) { b0 = __ldcg(vb + (k + 1) * 64); b1 = __ldcg(vb + (k + 1) * 64 + 32); }
            int oij = w * 36 + k;
            ull sa, sb;
            { ull d0 = f2add(h2w(a0.x), nmu0[0]); sa = f2mul(d0, d0);
              ull d1 = f2add(h2w(a0.y), nmu0[1]); sb = f2mul(d1, d1); }
            { ull d0 = f2add(h2w(a0.z), nmu0[2]); sa = f2fma(d0, d0, sa);
              ull d1 = f2add(h2w(a0.w), nmu0[3]); sb = f2fma(d1, d1, sb); }
            { ull d0 = f2add(h2w(a1.x), nmu1[0]); sa = f2fma(d0, d0, sa);
              ull d1 = f2add(h2w(a1.y), nmu1[1]); sb = f2fma(d1, d1, sb); }
            { ull d0 = f2add(h2w(a1.z), nmu1[2]); sa = f2fma(d0, d0, sa);
              ull d1 = f2add(h2w(a1.w), nmu1[3]); sb = f2fma(d1, d1, sb); }
            float slo, shi; f2unpack(slo, shi, f2add(sa, sb));
            float ph = sf * __expf(-(slo + shi));
            int o = oij / 9, ij = oij - o * 9;
            int i2 = ij / 3, j2 = ij - i2 * 3;
            int ip = (3 - i2) % 3, jp = (3 - j2) % 3;
            phb[(o * 9 + ip * 3 + jp) * 32] = ph;
            float T = ph;
            #pragma unroll
            for (int s = 16; s > 0; s >>= 1) T += __shfl_xor_sync(0xffffffffu, T, s);
            if (c == 0)
                atomicAdd(&g_D0[(n * 32 + o) * 169 + (2 * X + ip) * 13 + (2 * Y + jp)], T);
            a0 = b0; a1 = b1;
        }
    }
}

// ===================== kernels B/C: read sweeps =====================
// smem: aD 288 | red 12672 | mom 1056 | mu 544 | sfac 32 = 14592 f
#define SMB_AD   0
#define SMB_RED  288
#define SMB_MOM  12960
#define SMB_MU   14016
#define SMB_SFAC 14560
#define SMB_FLOATS 14592

template <int ITER>
__global__ void __launch_bounds__(384, 2) kBC(
    const float* __restrict__ x,
    const float* __restrict__ bv_p,
    const float* __restrict__ ba_p,
    const float* __restrict__ lam_p,
    float* __restrict__ out)
{
    extern __shared__ float sm[];
    float* aD_s   = sm + SMB_AD;
    float* red    = sm + SMB_RED;
    float* mom    = sm + SMB_MOM;
    float* mu_s   = sm + SMB_MU;
    float* sfac_s = sm + SMB_SFAC;

    const int xy = blockIdx.x, n = blockIdx.y;
    const int X = xy / 6, Y = xy % 6;
    const int tid = threadIdx.x;
    const int w = tid >> 5, c = tid & 31;   // 12 warps, 24 positions each
    const int base = (2 * X) * 13 + 2 * Y;

    const float* Din = (ITER == 1) ? g_D0 : g_D1;
    if (tid < 288) {
        int o = tid / 9, ij = tid - o * 9;
        float a = x[n * 91936 + (512 + o) * 169 + base + (ij / 3) * 13 + (ij % 3)];
        float Dv = __ldcg(&Din[(n * 32 + o) * 169 + (2 * X + ij / 3) * 13 + (2 * Y + ij % 3)]);
        aD_s[tid] = __fdividef(a, Dv);
    }
    __syncthreads();

    const float bv = bv_p[0], ba = ba_p[0], lam = lam_p[0];
    const uint4* vb = (const uint4*)g_votes + (((n * 36 + xy) * 288 + w * 24) * 2) * 32 + c;
    const float* phb = g_ph + ((n * 36 + xy) * 288 + w * 24) * 32 + c;

    // ---- M-read: moments over 24 positions ----
    ull m1a[4], m1b[4], m2a[4], m2b[4];
    #pragma unroll
    for (int r = 0; r < 4; r++) { m1a[r]=0ull; m1b[r]=0ull; m2a[r]=0ull; m2b[r]=0ull; }
    float sumr = 0.0f;
    {
        uint4 a0 = __ldcg(vb), a1 = __ldcg(vb + 32);
        #pragma unroll 4
        for (int k = 0; k < 24; k++) {
            uint4 b0 = a0, b1 = a1;
            if (k < 23) { b0 = __ldcg(vb + (k + 1) * 64); b1 = __ldcg(vb + (k + 1) * 64 + 32); }
            int oij = w * 24 + k;
            float rh = __ldcg(phb + k * 32) * aD_s[oij];
            sumr += rh;
            ull rh2 = f2pack(rh, rh);
            ull sv0[4], sv1[4];
            sv0[0] = h2w(a0.x); sv0[1] = h2w(a0.y); sv0[2] = h2w(a0.z); sv0[3] = h2w(a0.w);
            sv1[0] = h2w(a1.x); sv1[1] = h2w(a1.y); sv1[2] = h2w(a1.z); sv1[3] = h2w(a1.w);
            #pragma unroll
            for (int r = 0; r < 4; r++) {
                ull t0 = f2mul(rh2, sv0[r]);
                m1a[r] = f2add(m1a[r], t0);
                m2a[r] = f2fma(t0, sv0[r], m2a[r]);
                ull t1 = f2mul(rh2, sv1[r]);
                m1b[r] = f2add(m1b[r], t1);
                m2b[r] = f2fma(t1, sv1[r], m2b[r]);
            }
            a0 = b0; a1 = b1;
        }
    }
    {
        float* myred = red + (w * 32 + c) * 33;
        #pragma unroll
        for (int r = 0; r < 4; r++) {
            float lo, hi;
            f2unpack(lo, hi, m1a[r]); myred[r]      = lo; myred[4 + r]  = hi;
            f2unpack(lo, hi, m1b[r]); myred[8 + r]  = lo; myred[12 + r] = hi;
            f2unpack(lo, hi, m2a[r]); myred[16 + r] = lo; myred[20 + r] = hi;
            f2unpack(lo, hi, m2b[r]); myred[24 + r] = lo; myred[28 + r] = hi;
        }
        myred[32] = sumr;
    }
    __syncthreads();
    for (int s = tid; s < 1056; s += 384) {
        float acc = 0.0f;
        #pragma unroll
        for (int ww = 0; ww < 12; ww++) acc += red[ww * 1056 + s];
        mom[s] = acc;
    }
    __syncthreads();

    if (tid < 32) {
        const float* mm = mom + tid * 33;
        float R = mm[32], invR = 1.0f / R, cs = 0.0f;
        #pragma unroll
        for (int d = 0; d < 16; d++) {
            float m  = mm[d] * invR;
            float sg = fmaf(-m, m, mm[16 + d] * invR);
            mu_s[tid * 17 + d] = m;
            cs += __logf(sg);
        }
        float cost = R * fmaf(16.0f, bv, cs);
        float act  = 1.0f / (1.0f + __expf(lam * (cost - ba)));
        if (ITER == 2) {
            float* on = out + (long)n * 19584 + xy;
            #pragma unroll
            for (int d = 0; d < 16; d++)
                on[(tid * 16 + d) * 36] = mu_s[tid * 17 + d];
            on[(512 + tid) * 36] = act;
        } else {
            sfac_s[tid] = act * __expf(-0.5f * fmaf(16.0f, LOG2PI, cs));
        }
    }
    if (ITER == 2) return;
    __syncthreads();

    // ---- E1: stream votes, p_hat -> global, D1 via shuffle ----
    {
        float sf = sfac_s[c];
        ull nmu0[4], nmu1[4];
        #pragma unroll
        for (int r = 0; r < 4; r++) {
            nmu0[r] = f2pack(-mu_s[c * 17 + r],     -mu_s[c * 17 + 4 + r]);
            nmu1[r] = f2pack(-mu_s[c * 17 + 8 + r], -mu_s[c * 17 + 12 + r]);
        }
        float* phw = g_ph + ((n * 36 + xy) * 288) * 32 + c;
        uint4 a0 = __ldcg(vb), a1 = __ldcg(vb + 32);
        #pragma unroll 4
        for (int k = 0; k < 24; k++) {
            uint4 b0 = a0, b1 = a1;
            if (k < 23) { b0 = __ldcg(vb + (k + 1) * 64); b1 = __ldcg(vb + (k + 1) * 64 + 32); }
            int oij = w * 24 + k;
            ull sa, sb;
            { ull d0 = f2add(h2w(a0.x), nmu0[0]); sa = f2mul(d0, d0);
              ull d1 = f2add(h2w(a0.y), nmu0[1]); sb = f2mul(d1, d1); }
            { ull d0 = f2add(h2w(a0.z), nmu0[2]); sa = f2fma(d0, d0, sa);
              ull d1 = f2add(h2w(a0.w), nmu0[3]); sb = f2fma(d1, d1, sb); }
            { ull d0 = f2add(h2w(a1.x), nmu1[0]); sa = f2fma(d0, d0, sa);
              ull d1 = f2add(h2w(a1.y), nmu1[1]); sb = f2fma(d1, d1, sb); }
            { ull d0 = f2add(h2w(a1.z), nmu1[2]); sa = f2fma(d0, d0, sa);
              ull d1 = f2add(h2w(a1.w), nmu1[3]); sb = f2fma(d1, d1, sb); }
            float slo, shi; f2unpack(slo, shi, f2add(sa, sb));
            float ph = sf * __expf(-(slo + shi));
            int o = oij / 9, ij = oij - o * 9;
            int i2 = ij / 3, j2 = ij - i2 * 3;
            int ip = (3 - i2) % 3, jp = (3 - j2) % 3;
            phw[(o * 9 + ip * 3 + jp) * 32] = ph;
            float T = ph;
            #pragma unroll
            for (int s = 16; s > 0; s >>= 1) T += __shfl_xor_sync(0xffffffffu, T, s);
            if (c == 0)
                atomicAdd(&g_D1[(n * 32 + o) * 169 + (2 * X + ip) * 13 + (2 * Y + jp)], T);
            a0 = b0; a1 = b1;
        }
    }
}

extern "C" void kernel_launch(void* const* d_in, const int* in_sizes, int n_in,
                              void* d_out, int out_size) {
    const float* x   = (const float*)d_in[0];
    const float* W   = (const float*)d_in[1];
    const float* bv  = (const float*)d_in[2];
    const float* ba  = (const float*)d_in[3];
    const float* lam = (const float*)d_in[4];
    float* out = (float*)d_out;

    const int smemA = SMA_FLOATS * 4;   // 78336 B
    const int smemB = SMB_FLOATS * 4;   // 58368 B
    cudaFuncSetAttribute(kA, cudaFuncAttributeMaxDynamicSharedMemorySize, smemA);
    cudaFuncSetAttribute(kBC<1>, cudaFuncAttributeMaxDynamicSharedMemorySize, smemB);
    cudaFuncSetAttribute(kBC<2>, cudaFuncAttributeMaxDynamicSharedMemorySize, smemB);

    dim3 grid(36, 8);
    prep_kernel<<<576, 256>>>(W);
    kA<<<grid, 256, smemA>>>(x, bv, ba, lam);
    kBC<1><<<grid, 384, smemB>>>(x, bv, ba, lam, out);
    kBC<2><<<grid, 384, smemB>>>(x, bv, ba, lam, out);
}